// round 2
// baseline (speedup 1.0000x reference)
#include <cuda_runtime.h>

#define BB   8
#define NN   128
#define COOR 3
#define FF   128
#define FILT 128

// Scratch: A' = x @ w1 + bv  and  C = x @ w2, each [B, N, COOR, FILT]
__device__ float g_A[BB * NN * COOR * FILT];
__device__ float g_C[BB * NN * COOR * FILT];

// ---------------------------------------------------------------------------
// Phase 1: tiny GEMM [3072, 128] @ [128, 256]  ->  g_A (with +bv), g_C
// 8 GEMM rows per block share the w-column loads. 128 threads = one k each.
// x tile stored TRANSPOSED in smem so per-f reads are 2 broadcast LDS.128.
// ---------------------------------------------------------------------------
__global__ __launch_bounds__(128) void phase1_kernel(
    const float* __restrict__ x,   // [B*N*COOR, F] flattened
    const float* __restrict__ w,   // [2F, FILT]
    const float* __restrict__ bv)  // [FILT]
{
    constexpr int ROWS = 8;
    const int r0 = blockIdx.x * ROWS;   // 0..3064
    const int k  = threadIdx.x;         // 0..127

    // xs[f][r]: transposed so xs[f][0..7] is contiguous (2 x float4 broadcast)
    __shared__ float xs[FF][ROWS];

    // Load 8 contiguous x rows coalesced as float4, scatter transposed.
    {
        const float4* xin = reinterpret_cast<const float4*>(x + (size_t)r0 * FF);
        #pragma unroll
        for (int t = threadIdx.x; t < ROWS * FF / 4; t += 128) {
            const float4 v = xin[t];
            const int r = (t * 4) / FF;        // source row
            const int f = (t * 4) % FF;        // source feature
            xs[f + 0][r] = v.x;
            xs[f + 1][r] = v.y;
            xs[f + 2][r] = v.z;
            xs[f + 3][r] = v.w;
        }
    }
    __syncthreads();

    float accA[ROWS], accC[ROWS];
    const float bvk = bv[k];
    #pragma unroll
    for (int r = 0; r < ROWS; r++) { accA[r] = bvk; accC[r] = 0.0f; }

    #pragma unroll 4
    for (int f = 0; f < FF; f++) {
        const float w1 = w[f * FILT + k];          // coalesced over threads
        const float w2 = w[(FF + f) * FILT + k];
        const float4 xa = *reinterpret_cast<const float4*>(&xs[f][0]);  // bcast
        const float4 xb = *reinterpret_cast<const float4*>(&xs[f][4]);  // bcast
        accA[0] = fmaf(xa.x, w1, accA[0]);  accC[0] = fmaf(xa.x, w2, accC[0]);
        accA[1] = fmaf(xa.y, w1, accA[1]);  accC[1] = fmaf(xa.y, w2, accC[1]);
        accA[2] = fmaf(xa.z, w1, accA[2]);  accC[2] = fmaf(xa.z, w2, accC[2]);
        accA[3] = fmaf(xa.w, w1, accA[3]);  accC[3] = fmaf(xa.w, w2, accC[3]);
        accA[4] = fmaf(xb.x, w1, accA[4]);  accC[4] = fmaf(xb.x, w2, accC[4]);
        accA[5] = fmaf(xb.y, w1, accA[5]);  accC[5] = fmaf(xb.y, w2, accC[5]);
        accA[6] = fmaf(xb.z, w1, accA[6]);  accC[6] = fmaf(xb.z, w2, accC[6]);
        accA[7] = fmaf(xb.w, w1, accA[7]);  accC[7] = fmaf(xb.w, w2, accC[7]);
    }

    #pragma unroll
    for (int r = 0; r < ROWS; r++) {
        g_A[(size_t)(r0 + r) * FILT + k] = accA[r];
        g_C[(size_t)(r0 + r) * FILT + k] = accC[r];
    }
}

// ---------------------------------------------------------------------------
// Phase 2: out[b,i,j,k] = sum_c (A'[b,i,c,k] + C[b,j,c,k]) * d[b,i,j,c]
// Block = (32,8): tx indexes k as float4, ty strides over j (16 iters).
// TI=4 i-rows per block; A' tile in registers; distances tile in smem.
// C loads (L2, ~234cyc) are software-pipelined one j-iteration ahead, and
// the 12 distance scalars are hoisted into registers before the FMA block.
// ---------------------------------------------------------------------------
__global__ __launch_bounds__(256) void phase2_kernel(
    const float* __restrict__ dist,  // [B, N, N, COOR]
    float* __restrict__ out)         // [B, N, N, FILT]
{
    constexpr int TI = 4;
    const int b  = blockIdx.y;
    const int i0 = blockIdx.x * TI;
    const int tx = threadIdx.x;   // 0..31
    const int ty = threadIdx.y;   // 0..7
    const int tid = ty * 32 + tx;

    __shared__ float sd[TI * NN * COOR];   // 1536 floats = 6 KB

    // Load distances slice d[b, i0:i0+4, :, :] (contiguous 1536 floats).
    {
        const float4* din =
            reinterpret_cast<const float4*>(dist + (size_t)(b * NN + i0) * NN * COOR);
        float4* sd4 = reinterpret_cast<float4*>(sd);
        #pragma unroll
        for (int t = tid; t < TI * NN * COOR / 4; t += 256) sd4[t] = din[t];
    }

    // A' tile into registers: 4 i x 3 c x float4 = 48 floats.
    float4 Ar[TI][COOR];
    {
        const float4* A4 = reinterpret_cast<const float4*>(g_A);
        #pragma unroll
        for (int i = 0; i < TI; i++)
            #pragma unroll
            for (int c = 0; c < COOR; c++)
                Ar[i][c] = A4[((size_t)(b * NN + i0 + i) * COOR + c) * (FILT / 4) + tx];
    }
    __syncthreads();

    const float4* C4 = reinterpret_cast<const float4*>(g_C) +
                       (size_t)b * NN * COOR * (FILT / 4) + tx;
    float4* out4 = reinterpret_cast<float4*>(out) +
                   ((size_t)(b * NN + i0) * NN) * (FILT / 4) + tx;

    // Prime the pipeline with j = ty.
    float4 c0 = C4[(size_t)ty * COOR * (FILT / 4) + 0 * (FILT / 4)];
    float4 c1 = C4[(size_t)ty * COOR * (FILT / 4) + 1 * (FILT / 4)];
    float4 c2 = C4[(size_t)ty * COOR * (FILT / 4) + 2 * (FILT / 4)];

    #pragma unroll
    for (int it = 0; it < NN / 8; it++) {
        const int j = ty + it * 8;

        // Prefetch next iteration's C before computing this one.
        float4 n0, n1, n2;
        if (it + 1 < NN / 8) {
            const size_t nb = (size_t)(j + 8) * COOR * (FILT / 4);
            n0 = C4[nb + 0 * (FILT / 4)];
            n1 = C4[nb + 1 * (FILT / 4)];
            n2 = C4[nb + 2 * (FILT / 4)];
        }

        // Hoist distance scalars (smem broadcast, 29cyc) before the FMA block.
        float dv[TI][COOR];
        #pragma unroll
        for (int i = 0; i < TI; i++) {
            dv[i][0] = sd[(i * NN + j) * COOR + 0];
            dv[i][1] = sd[(i * NN + j) * COOR + 1];
            dv[i][2] = sd[(i * NN + j) * COOR + 2];
        }

        #pragma unroll
        for (int i = 0; i < TI; i++) {
            const float d0 = dv[i][0], d1 = dv[i][1], d2 = dv[i][2];
            float4 o;
            o.x = fmaf(Ar[i][0].x + c0.x, d0,
                  fmaf(Ar[i][1].x + c1.x, d1, (Ar[i][2].x + c2.x) * d2));
            o.y = fmaf(Ar[i][0].y + c0.y, d0,
                  fmaf(Ar[i][1].y + c1.y, d1, (Ar[i][2].y + c2.y) * d2));
            o.z = fmaf(Ar[i][0].z + c0.z, d0,
                  fmaf(Ar[i][1].z + c1.z, d1, (Ar[i][2].z + c2.z) * d2));
            o.w = fmaf(Ar[i][0].w + c0.w, d0,
                  fmaf(Ar[i][1].w + c1.w, d1, (Ar[i][2].w + c2.w) * d2));
            out4[((size_t)i * NN + j) * (FILT / 4)] = o;
        }

        c0 = n0; c1 = n1; c2 = n2;
    }
}

extern "C" void kernel_launch(void* const* d_in, const int* in_sizes, int n_in,
                              void* d_out, int out_size)
{
    const float* x    = (const float*)d_in[0];  // vector_features [8,128,3,128]
    const float* dist = (const float*)d_in[1];  // distances       [8,128,128,3]
    const float* w    = (const float*)d_in[2];  // w_vs            [256,128]
    const float* bv   = (const float*)d_in[3];  // b_vs            [128]
    float* out = (float*)d_out;                 // [8,128,128,128]

    (void)in_sizes; (void)n_in; (void)out_size;

    phase1_kernel<<<(BB * NN * COOR) / 8, 128>>>(x, w, bv);
    phase2_kernel<<<dim3(NN / 4, BB), dim3(32, 8)>>>(dist, out);
}